// round 4
// baseline (speedup 1.0000x reference)
#include <cuda_runtime.h>

#define HW (512 * 512)
#define EPS 1e-6f

// 2 pixels per thread: doubles independent load chains for latency hiding.
__global__ __launch_bounds__(256) void Interpolate_28664611734214_kernel(
    const float4* __restrict__ data4,    // (9,9,512,512,3) viewed as float4 chunks
    const float*  __restrict__ cam_xyz,  // (3,)
    const int*    __restrict__ neighbors,// (4,2)
    const int4*   __restrict__ uv4,      // (4,512,512,2) as int4 (2 pixels/elem)
    float2*       __restrict__ out2)     // flat (HW,3) as float2 (aligned: 24B/thread)
{
    const int tid = blockIdx.x * blockDim.x + threadIdx.x;   // pixel pair id
    if (tid >= HW / 2) return;

    // ---- weights (tiny; all loads L1-broadcast) ----
    const float c0 = __ldg(cam_xyz + 0);
    const float c1 = __ldg(cam_xyz + 1);

    int n0[4], n1[4];
    float t[4];
#pragma unroll
    for (int j = 0; j < 4; j++) {
        n0[j] = __ldg(neighbors + 2 * j + 0);
        n1[j] = __ldg(neighbors + 2 * j + 1);
        const float d0 = c0 - (float)n0[j];
        const float d1 = c1 - (float)n1[j];
        float v = fabsf(d0 * d1);
        t[j] = (v <= EPS) ? 0.0f : v;   // threshold BEFORE sum (matches ref)
    }
    const float s = t[0] + t[1] + t[2] + t[3];

    float w[4];
#pragma unroll
    for (int n = 0; n < 4; n++) {
        // flip: weight for gathered[n] pairs with t of neighbor (3-n)
        const float x = t[3 - n] / s;
        w[n] = (fabsf(x) <= EPS) ? 0.0f : x;
    }

    // ---- gather both pixels of the pair; 8 independent chains ----
    float r0 = 0.f, g0 = 0.f, b0 = 0.f;
    float r1 = 0.f, g1 = 0.f, b1 = 0.f;

#pragma unroll
    for (int n = 0; n < 4; n++) {
        const int4 q = __ldg(uv4 + n * (HW / 2) + tid);  // (u0,v0,u1,v1)
        const int base = (n0[n] * 9 + n1[n]) * (512 * 512);
        const float wn = w[n];

        // --- pixel 0 ---
        {
            const int f     = (base + q.x * 512 + q.y) * 3;
            const int chunk = f >> 2;
            const int o     = f & 3;
            const float4 A = __ldg(data4 + chunk);
            float4 B = make_float4(0.f, 0.f, 0.f, 0.f);
            if (o >= 2) B = __ldg(data4 + chunk + 1);
            float rr, gg, bb;
            if (o == 0)      { rr = A.x; gg = A.y; bb = A.z; }
            else if (o == 1) { rr = A.y; gg = A.z; bb = A.w; }
            else if (o == 2) { rr = A.z; gg = A.w; bb = B.x; }
            else             { rr = A.w; gg = B.x; bb = B.y; }
            r0 += wn * rr; g0 += wn * gg; b0 += wn * bb;
        }
        // --- pixel 1 ---
        {
            const int f     = (base + q.z * 512 + q.w) * 3;
            const int chunk = f >> 2;
            const int o     = f & 3;
            const float4 A = __ldg(data4 + chunk);
            float4 B = make_float4(0.f, 0.f, 0.f, 0.f);
            if (o >= 2) B = __ldg(data4 + chunk + 1);
            float rr, gg, bb;
            if (o == 0)      { rr = A.x; gg = A.y; bb = A.z; }
            else if (o == 1) { rr = A.y; gg = A.z; bb = A.w; }
            else if (o == 2) { rr = A.z; gg = A.w; bb = B.x; }
            else             { rr = A.w; gg = B.x; bb = B.y; }
            r1 += wn * rr; g1 += wn * gg; b1 += wn * bb;
        }
    }

    // (HW,3) interleaved layout: this pair owns floats [6*tid, 6*tid+6)
    out2[3 * tid + 0] = make_float2(r0, g0);
    out2[3 * tid + 1] = make_float2(b0, r1);
    out2[3 * tid + 2] = make_float2(g1, b1);
}

extern "C" void kernel_launch(void* const* d_in, const int* in_sizes, int n_in,
                              void* d_out, int out_size) {
    // metadata order: data, pixel, cam_xyz, neighbors, uv
    const float4* data4     = (const float4*)d_in[0];
    // d_in[1] = pixel, only its shape is used by the reference -> unused here
    const float*  cam_xyz   = (const float*)d_in[2];
    const int*    neighbors = (const int*)d_in[3];
    const int4*   uv4       = (const int4*)d_in[4];
    float2*       out2      = (float2*)d_out;

    const int threads = 256;
    const int pairs   = HW / 2;                          // 131072
    const int blocks  = (pairs + threads - 1) / threads; // 512
    Interpolate_28664611734214_kernel<<<blocks, threads>>>(
        data4, cam_xyz, neighbors, uv4, out2);
}

// round 5
// speedup vs baseline: 1.0025x; 1.0025x over previous
#include <cuda_runtime.h>
#include <cstdint>

#define HW (512 * 512)
#define EPS 1e-6f

__global__ __launch_bounds__(256) void Interpolate_28664611734214_kernel(
    const float4* __restrict__ data4,    // (9,9,512,512,3) viewed as float4 chunks
    const float*  __restrict__ cam_xyz,  // (3,)
    const int*    __restrict__ neighbors,// (4,2)
    const int2*   __restrict__ uv,       // (4,512,512,2) as int2
    float*        __restrict__ out)      // flat (HW,3) == reshape(3,H,W)
{
    const int pix = blockIdx.x * blockDim.x + threadIdx.x;
    if (pix >= HW) return;

    // ---- weights (tiny; all loads L1-broadcast) ----
    const float c0 = __ldg(cam_xyz + 0);
    const float c1 = __ldg(cam_xyz + 1);

    int n0[4], n1[4];
    float t[4];
#pragma unroll
    for (int j = 0; j < 4; j++) {
        n0[j] = __ldg(neighbors + 2 * j + 0);
        n1[j] = __ldg(neighbors + 2 * j + 1);
        const float d0 = c0 - (float)n0[j];
        const float d1 = c1 - (float)n1[j];
        float v = fabsf(d0 * d1);
        t[j] = (v <= EPS) ? 0.0f : v;   // threshold BEFORE sum (matches ref)
    }
    const float s = t[0] + t[1] + t[2] + t[3];

    float w[4];
#pragma unroll
    for (int n = 0; n < 4; n++) {
        // flip: weight for gathered[n] pairs with t of neighbor (3-n)
        const float x = t[3 - n] / s;
        w[n] = (fabsf(x) <= EPS) ? 0.0f : x;
    }

    // ---- phase 1: issue ALL uv loads (forced order via asm volatile) ----
    int qu[4], qv[4];
#pragma unroll
    for (int n = 0; n < 4; n++) {
        const int2* p = uv + n * HW + pix;
        asm volatile("ld.global.nc.v2.u32 {%0, %1}, [%2];"
                     : "=r"(qu[n]), "=r"(qv[n]) : "l"(p));
    }

    // ---- phase 2: compute addresses, issue ALL gather loads before use ----
    const float4* pA[4];
    int o[4];
#pragma unroll
    for (int n = 0; n < 4; n++) {
        const int f = (((n0[n] * 9 + n1[n]) * 512 + qu[n]) * 512 + qv[n]) * 3;
        pA[n] = data4 + (f >> 2);
        o[n]  = f & 3;
    }

    float4 A[4], B[4];
#pragma unroll
    for (int n = 0; n < 4; n++) {
        asm volatile("ld.global.nc.v4.f32 {%0, %1, %2, %3}, [%4];"
                     : "=f"(A[n].x), "=f"(A[n].y), "=f"(A[n].z), "=f"(A[n].w)
                     : "l"(pA[n]));
    }
#pragma unroll
    for (int n = 0; n < 4; n++) {
        // predicated: only ~half the lanes need the second chunk (o >= 2).
        // When the predicate is false, B[n] is unused garbage routed through
        // selp arms that o never selects.
        asm volatile("{\n\t"
                     ".reg .pred p;\n\t"
                     "setp.ge.s32 p, %5, 2;\n\t"
                     "@p ld.global.nc.v4.f32 {%0, %1, %2, %3}, [%4];\n\t"
                     "}"
                     : "=f"(B[n].x), "=f"(B[n].y), "=f"(B[n].z), "=f"(B[n].w)
                     : "l"(pA[n] + 1), "r"(o[n]));
    }

    // ---- phase 3: consume (by now all 8+4 loads are in flight) ----
    float r = 0.f, g = 0.f, b = 0.f;
#pragma unroll
    for (int n = 0; n < 4; n++) {
        const int oo = o[n];
        float rr, gg, bb;
        if (oo == 0)      { rr = A[n].x; gg = A[n].y; bb = A[n].z; }
        else if (oo == 1) { rr = A[n].y; gg = A[n].z; bb = A[n].w; }
        else if (oo == 2) { rr = A[n].z; gg = A[n].w; bb = B[n].x; }
        else              { rr = A[n].w; gg = B[n].x; bb = B[n].y; }
        const float wn = w[n];
        r += wn * rr; g += wn * gg; b += wn * bb;
    }

    // (HW,3) interleaved layout
    out[3 * pix + 0] = r;
    out[3 * pix + 1] = g;
    out[3 * pix + 2] = b;
}

extern "C" void kernel_launch(void* const* d_in, const int* in_sizes, int n_in,
                              void* d_out, int out_size) {
    // metadata order: data, pixel, cam_xyz, neighbors, uv
    const float4* data4     = (const float4*)d_in[0];
    // d_in[1] = pixel, only its shape is used by the reference -> unused here
    const float*  cam_xyz   = (const float*)d_in[2];
    const int*    neighbors = (const int*)d_in[3];
    const int2*   uv        = (const int2*)d_in[4];
    float*        out       = (float*)d_out;

    const int threads = 256;
    const int blocks  = (HW + threads - 1) / threads;  // 1024
    Interpolate_28664611734214_kernel<<<blocks, threads>>>(
        data4, cam_xyz, neighbors, uv, out);
}

// round 6
// speedup vs baseline: 1.0226x; 1.0201x over previous
#include <cuda_runtime.h>

#define HW (512 * 512)
#define EPS 1e-6f

__global__ __launch_bounds__(128) void Interpolate_28664611734214_kernel(
    const float4* __restrict__ data4,    // (9,9,512,512,3) viewed as float4 chunks
    const float*  __restrict__ cam_xyz,  // (3,)
    const int*    __restrict__ neighbors,// (4,2)
    const int2*   __restrict__ uv,       // (4,512,512,2) as int2
    float*        __restrict__ out)      // flat (HW,3) == reshape(3,H,W)
{
    const int pix = blockIdx.x * blockDim.x + threadIdx.x;   // grid tiles HW exactly

    // ---- head of the critical path: issue all 4 uv loads first ----
    int2 q[4];
#pragma unroll
    for (int n = 0; n < 4; n++)
        q[n] = __ldg(uv + n * HW + pix);

    // ---- weights (tiny; all loads L1-broadcast; fills the uv-load shadow) ----
    const float c0 = __ldg(cam_xyz + 0);
    const float c1 = __ldg(cam_xyz + 1);

    int n0[4], n1[4];
    float t[4];
#pragma unroll
    for (int j = 0; j < 4; j++) {
        n0[j] = __ldg(neighbors + 2 * j + 0);
        n1[j] = __ldg(neighbors + 2 * j + 1);
        const float d0 = c0 - (float)n0[j];
        const float d1 = c1 - (float)n1[j];
        float v = fabsf(d0 * d1);
        t[j] = (v <= EPS) ? 0.0f : v;   // threshold BEFORE sum (matches ref)
    }
    const float s = t[0] + t[1] + t[2] + t[3];

    float w[4];
#pragma unroll
    for (int n = 0; n < 4; n++) {
        // flip: weight for gathered[n] pairs with t of neighbor (3-n)
        const float x = t[3 - n] / s;
        w[n] = (fabsf(x) <= EPS) ? 0.0f : x;
    }

    // ---- gather + weighted sum (compiler-scheduled; R3-style) ----
    float r = 0.f, g = 0.f, b = 0.f;
#pragma unroll
    for (int n = 0; n < 4; n++) {
        // float index of R channel: f = 3 * point_idx  (< 64M, fits int32)
        const int f     = (((n0[n] * 9 + n1[n]) * 512 + q[n].x) * 512 + q[n].y) * 3;
        const int chunk = f >> 2;       // float4 index
        const int o     = f & 3;        // offset within chunk

        const float4 A = __ldg(data4 + chunk);
        float2 B = make_float2(0.f, 0.f);
        if (o >= 2)                      // predicated; ~half the lanes
            B = __ldg((const float2*)(data4 + chunk + 1));

        float rr, gg, bb;
        if (o == 0)      { rr = A.x; gg = A.y; bb = A.z; }
        else if (o == 1) { rr = A.y; gg = A.z; bb = A.w; }
        else if (o == 2) { rr = A.z; gg = A.w; bb = B.x; }
        else             { rr = A.w; gg = B.x; bb = B.y; }

        const float wn = w[n];
        r += wn * rr;
        g += wn * gg;
        b += wn * bb;
    }

    // einsum result is (HW,3) then reinterpreted as (3,H,W): interleaved layout
    out[3 * pix + 0] = r;
    out[3 * pix + 1] = g;
    out[3 * pix + 2] = b;
}

extern "C" void kernel_launch(void* const* d_in, const int* in_sizes, int n_in,
                              void* d_out, int out_size) {
    // metadata order: data, pixel, cam_xyz, neighbors, uv
    const float4* data4     = (const float4*)d_in[0];
    // d_in[1] = pixel, only its shape is used by the reference -> unused here
    const float*  cam_xyz   = (const float*)d_in[2];
    const int*    neighbors = (const int*)d_in[3];
    const int2*   uv        = (const int2*)d_in[4];
    float*        out       = (float*)d_out;

    const int threads = 128;
    const int blocks  = HW / threads;   // 2048, tiles HW exactly
    Interpolate_28664611734214_kernel<<<blocks, threads>>>(
        data4, cam_xyz, neighbors, uv, out);
}